// round 1
// baseline (speedup 1.0000x reference)
#include <cuda_runtime.h>
#include <math.h>

// ---------------------------------------------------------------------------
// Problem constants
// ---------------------------------------------------------------------------
#define B_   64
#define P_   225
#define K_   16
#define D_   640
#define MQ   (B_ * P_)      // 14400 query rows
#define NR   (K_ * P_)      // 3600 reference rows

// ---------------------------------------------------------------------------
// Scratch (allocation-free: __device__ globals)
// ---------------------------------------------------------------------------
__device__ float g_qn[MQ * D_];      // normalized q_patch
__device__ float g_rn[NR * D_];      // normalized r_patch
__device__ float g_amap[MQ];         // 0.5*(1 - max sim)
__device__ float g_famean[D_];       // mean adapter output

// ---------------------------------------------------------------------------
// Kernel 1: row L2-normalize (x / (||x|| + 1e-6)), D=640 per row
// ---------------------------------------------------------------------------
__global__ void norm_rows_kernel(const float* __restrict__ in,
                                 float* __restrict__ out) {
    const int row = blockIdx.x;
    const float* x = in + (size_t)row * D_;
    float ss = 0.f;
    for (int i = threadIdx.x; i < D_; i += blockDim.x) {
        float v = x[i];
        ss = fmaf(v, v, ss);
    }
    // warp reduce
    #pragma unroll
    for (int o = 16; o > 0; o >>= 1) ss += __shfl_xor_sync(0xffffffffu, ss, o);
    __shared__ float wsum[4];
    const int lane = threadIdx.x & 31, warp = threadIdx.x >> 5;
    if (lane == 0) wsum[warp] = ss;
    __syncthreads();
    float total = wsum[0] + wsum[1] + wsum[2] + wsum[3];
    const float scale = 1.f / (sqrtf(total) + 1e-6f);
    float* o = out + (size_t)row * D_;
    for (int i = threadIdx.x; i < D_; i += blockDim.x)
        o[i] = x[i] * scale;
}

// ---------------------------------------------------------------------------
// Kernel 2: fused GEMM + row-max: amap[m] = 0.5*(1 - max_n dot(qn[m], rn[n]))
// 64x64 block tile, 4x4 per-thread micro-tile, BK=32, float4 smem reads.
// ---------------------------------------------------------------------------
#define BM 64
#define BN 64
#define BK 32
#define NT ((NR + BN - 1) / BN)   // 57
#define KT (D_ / BK)              // 20

__global__ __launch_bounds__(256, 2)
void gemm_max_kernel() {
    __shared__ __align__(16) float As[BK][BM + 4];
    __shared__ __align__(16) float Bs[BK][BN + 4];

    const int tx = threadIdx.x & 15;        // 0..15 -> N
    const int ty = threadIdx.x >> 4;        // 0..15 -> M
    const int rowBase = blockIdx.x * BM;

    float runmax[4] = {-1e30f, -1e30f, -1e30f, -1e30f};

    for (int nt = 0; nt < NT; ++nt) {
        const int nBase = nt * BN;
        float acc[4][4];
        #pragma unroll
        for (int i = 0; i < 4; ++i)
            #pragma unroll
            for (int j = 0; j < 4; ++j) acc[i][j] = 0.f;

        for (int kt = 0; kt < KT; ++kt) {
            const int k0 = kt * BK;
            // Load A tile (64x32) transposed into As[k][m], coalesced on k
            #pragma unroll
            for (int it = 0; it < 8; ++it) {
                int idx = threadIdx.x + it * 256;
                int m = idx >> 5, k = idx & 31;
                As[k][m] = g_qn[(size_t)(rowBase + m) * D_ + k0 + k];
            }
            // Load B tile (64x32) transposed, zero-pad rows >= NR
            #pragma unroll
            for (int it = 0; it < 8; ++it) {
                int idx = threadIdx.x + it * 256;
                int n = idx >> 5, k = idx & 31;
                int gn = nBase + n;
                Bs[k][n] = (gn < NR) ? g_rn[(size_t)gn * D_ + k0 + k] : 0.f;
            }
            __syncthreads();
            #pragma unroll
            for (int k = 0; k < BK; ++k) {
                float4 a4 = *(const float4*)&As[k][ty * 4];
                float4 b4 = *(const float4*)&Bs[k][tx * 4];
                float av[4] = {a4.x, a4.y, a4.z, a4.w};
                float bv[4] = {b4.x, b4.y, b4.z, b4.w};
                #pragma unroll
                for (int i = 0; i < 4; ++i)
                    #pragma unroll
                    for (int j = 0; j < 4; ++j)
                        acc[i][j] = fmaf(av[i], bv[j], acc[i][j]);
            }
            __syncthreads();
        }
        // fold this n-tile into running max (mask padded columns)
        #pragma unroll
        for (int j = 0; j < 4; ++j) {
            if (nBase + tx * 4 + j < NR) {
                #pragma unroll
                for (int i = 0; i < 4; ++i)
                    runmax[i] = fmaxf(runmax[i], acc[i][j]);
            }
        }
    }

    // cross-thread (over tx) max reduction per row
    __shared__ float red[BM][17];
    #pragma unroll
    for (int i = 0; i < 4; ++i) red[ty * 4 + i][tx] = runmax[i];
    __syncthreads();
    if (threadIdx.x < BM) {
        int r = threadIdx.x;
        float m = red[r][0];
        #pragma unroll
        for (int t = 1; t < 16; ++t) m = fmaxf(m, red[r][t]);
        g_amap[rowBase + r] = 0.5f * (1.f - m);
    }
}

// ---------------------------------------------------------------------------
// Kernel 3: adapter. famean = mean_k relu(relu(r_img @ w1) @ w2)
// r_img [16,640], w1 [640,160], w2 [160,640]
// ---------------------------------------------------------------------------
__global__ void adapter_kernel(const float* __restrict__ r_img,
                               const float* __restrict__ w1,
                               const float* __restrict__ w2) {
    __shared__ float h1[K_ * 160];
    for (int idx = threadIdx.x; idx < K_ * 160; idx += blockDim.x) {
        int k = idx / 160, i = idx % 160;
        float s = 0.f;
        const float* xr = r_img + k * D_;
        for (int d = 0; d < D_; ++d) s = fmaf(xr[d], w1[d * 160 + i], s);
        h1[idx] = fmaxf(s, 0.f);
    }
    __syncthreads();
    for (int j = threadIdx.x; j < D_; j += blockDim.x) {
        float acc = 0.f;
        for (int k = 0; k < K_; ++k) {
            float s = 0.f;
            const float* h = h1 + k * 160;
            for (int i = 0; i < 160; ++i) s = fmaf(h[i], w2[i * D_ + j], s);
            acc += fmaxf(s, 0.f);
        }
        g_famean[j] = acc * (1.f / (float)K_);
    }
}

// ---------------------------------------------------------------------------
// Kernel 4: both heads + final score, one block per batch element b.
// head(x): bn(relu(x@w1+b1),g2,be2) -> bn(relu(.@w2+b2),g3,be3) -> sigmoid(.@w3+b3)
// out[b] = 0.5*(s_ref + s_map) + mean_p amap[b,p]
// ---------------------------------------------------------------------------
__global__ void heads_kernel(
    const float* __restrict__ q_img,
    const float* __restrict__ dh_w1, const float* __restrict__ dh_b1,
    const float* __restrict__ dh_g2, const float* __restrict__ dh_be2,
    const float* __restrict__ dh_w2, const float* __restrict__ dh_b2,
    const float* __restrict__ dh_g3, const float* __restrict__ dh_be3,
    const float* __restrict__ dh_w3, const float* __restrict__ dh_b3,
    const float* __restrict__ dr_w1, const float* __restrict__ dr_b1,
    const float* __restrict__ dr_g2, const float* __restrict__ dr_be2,
    const float* __restrict__ dr_w2, const float* __restrict__ dr_b2,
    const float* __restrict__ dr_g3, const float* __restrict__ dr_be3,
    const float* __restrict__ dr_w3, const float* __restrict__ dr_b3,
    float* __restrict__ out) {
    const int b = blockIdx.x;
    const int t = threadIdx.x;          // 128 threads
    __shared__ float xr[D_];
    __shared__ float am[P_];
    __shared__ float h1[128];
    __shared__ float h2[64];
    __shared__ float s_ref_s, s_map_s, mean_s;

    for (int i = t; i < D_; i += 128) xr[i] = q_img[b * D_ + i] - g_famean[i];
    for (int i = t; i < P_; i += 128) am[i] = g_amap[b * P_ + i];
    __syncthreads();

    // ---- dr head on xr (640 -> 128 -> 64 -> 1) ----
    {
        float s = dr_b1[t];
        for (int d = 0; d < D_; ++d) s = fmaf(xr[d], dr_w1[d * 128 + t], s);
        h1[t] = fmaxf(s, 0.f) * dr_g2[t] + dr_be2[t];
    }
    __syncthreads();
    if (t < 64) {
        float s = dr_b2[t];
        for (int i = 0; i < 128; ++i) s = fmaf(h1[i], dr_w2[i * 64 + t], s);
        h2[t] = fmaxf(s, 0.f) * dr_g3[t] + dr_be3[t];
    }
    __syncthreads();
    if (t == 0) {
        float s = dr_b3[0];
        for (int i = 0; i < 64; ++i) s = fmaf(h2[i], dr_w3[i], s);
        s_ref_s = 1.f / (1.f + expf(-s));
    }
    __syncthreads();

    // ---- dh head on am (225 -> 128 -> 64 -> 1) ----
    {
        float s = dh_b1[t];
        for (int p = 0; p < P_; ++p) s = fmaf(am[p], dh_w1[p * 128 + t], s);
        h1[t] = fmaxf(s, 0.f) * dh_g2[t] + dh_be2[t];
    }
    __syncthreads();
    if (t < 64) {
        float s = dh_b2[t];
        for (int i = 0; i < 128; ++i) s = fmaf(h1[i], dh_w2[i * 64 + t], s);
        h2[t] = fmaxf(s, 0.f) * dh_g3[t] + dh_be3[t];
    }
    __syncthreads();
    if (t == 0) {
        float s = dh_b3[0];
        for (int i = 0; i < 64; ++i) s = fmaf(h2[i], dh_w3[i], s);
        s_map_s = 1.f / (1.f + expf(-s));
        float msum = 0.f;
        for (int p = 0; p < P_; ++p) msum += am[p];
        mean_s = msum / (float)P_;
        out[b] = 0.5f * (s_ref_s + s_map_s) + mean_s;
    }
}

// ---------------------------------------------------------------------------
// Launch
// ---------------------------------------------------------------------------
extern "C" void kernel_launch(void* const* d_in, const int* in_sizes, int n_in,
                              void* d_out, int out_size) {
    const float* q_patch = (const float*)d_in[0];
    const float* r_patch = (const float*)d_in[1];
    const float* q_img   = (const float*)d_in[2];
    const float* r_img   = (const float*)d_in[3];
    const float* adpt_w1 = (const float*)d_in[4];
    const float* adpt_w2 = (const float*)d_in[5];
    // dh params: indices 6..15 ; dr params: indices 16..25
    const float* dh_w1  = (const float*)d_in[6];
    const float* dh_b1  = (const float*)d_in[7];
    const float* dh_g2  = (const float*)d_in[8];
    const float* dh_be2 = (const float*)d_in[9];
    const float* dh_w2  = (const float*)d_in[10];
    const float* dh_b2  = (const float*)d_in[11];
    const float* dh_g3  = (const float*)d_in[12];
    const float* dh_be3 = (const float*)d_in[13];
    const float* dh_w3  = (const float*)d_in[14];
    const float* dh_b3  = (const float*)d_in[15];
    const float* dr_w1  = (const float*)d_in[16];
    const float* dr_b1  = (const float*)d_in[17];
    const float* dr_g2  = (const float*)d_in[18];
    const float* dr_be2 = (const float*)d_in[19];
    const float* dr_w2  = (const float*)d_in[20];
    const float* dr_b2  = (const float*)d_in[21];
    const float* dr_g3  = (const float*)d_in[22];
    const float* dr_be3 = (const float*)d_in[23];
    const float* dr_w3  = (const float*)d_in[24];
    const float* dr_b3  = (const float*)d_in[25];
    float* out = (float*)d_out;

    float *qn_ptr = nullptr, *rn_ptr = nullptr;
    cudaGetSymbolAddress((void**)&qn_ptr, g_qn);
    cudaGetSymbolAddress((void**)&rn_ptr, g_rn);

    norm_rows_kernel<<<MQ, 128>>>(q_patch, qn_ptr);
    norm_rows_kernel<<<NR, 128>>>(r_patch, rn_ptr);
    gemm_max_kernel<<<MQ / BM, 256>>>();
    adapter_kernel<<<1, 256>>>(r_img, adpt_w1, adpt_w2);
    heads_kernel<<<B_, 128>>>(q_img,
                              dh_w1, dh_b1, dh_g2, dh_be2, dh_w2, dh_b2,
                              dh_g3, dh_be3, dh_w3, dh_b3,
                              dr_w1, dr_b1, dr_g2, dr_be2, dr_w2, dr_b2,
                              dr_g3, dr_be3, dr_w3, dr_b3,
                              out);
}